// round 2
// baseline (speedup 1.0000x reference)
#include <cuda_runtime.h>
#include <math.h>

#define NN 4000
#define BB 4
#define FF 16
#define TT 16
#define OO 16

// ---------------- scratch (device globals; no allocation allowed) ----------------
__device__ float g_u2u3[NN];
__device__ float g_tlhs[BB*TT];
__device__ float g_trhs[BB*TT];
__device__ float g_E[BB*TT*TT];
__device__ float g_xTAt[BB*NN*FF*TT];
__device__ float g_slhs[BB*NN*FF];
__device__ float g_srhs[BB*NN*FF];
__device__ float g_sigP[64000000];   // [B][N][N] 256MB
__device__ float g_S[64000000];      // [B][N][N] 256MB
__device__ float g_Tx0[BB*NN*FF*TT];
__device__ float g_Tx1[BB*NN*FF*TT];
__device__ float g_Tx2[BB*NN*FF*TT];
__device__ float g_y[BB*NN*OO];
__device__ float g_stats[BB*2];

__device__ __forceinline__ float sigmoidf_(float v){ return 1.f/(1.f+expf(-v)); }

// ---------------- packed f32x2 helpers (Blackwell full-rate fp32) ----------------
__device__ __forceinline__ unsigned long long pack2(float x, float y){
    unsigned long long r;
    asm("mov.b64 %0, {%1, %2};" : "=l"(r) : "f"(x), "f"(y));
    return r;
}
__device__ __forceinline__ void fma2(unsigned long long &d, unsigned long long a, unsigned long long b){
    asm("fma.rn.f32x2 %0, %1, %2, %0;" : "+l"(d) : "l"(a), "l"(b));
}
__device__ __forceinline__ float2 unpack2(unsigned long long v){
    float2 f; asm("mov.b64 {%0, %1}, %2;" : "=f"(f.x), "=f"(f.y) : "l"(v)); return f;
}

// ---------------- small kernels ----------------
__global__ void k_u2u3(const float* __restrict__ U2, const float* __restrict__ U3){
    int n = blockIdx.x*blockDim.x + threadIdx.x;
    if (n < NN){
        float s = 0.f;
        #pragma unroll
        for (int g=0; g<FF; g++) s += U2[g*NN+n]*U3[g];
        g_u2u3[n] = s;
    }
}

__global__ void k_tred(const float* __restrict__ x, const float* __restrict__ U1){
    int b = blockIdx.x >> 4, t = blockIdx.x & 15;
    int tid = threadIdx.x;
    float s1 = 0.f, s2 = 0.f;
    for (int i = tid; i < NN*FF; i += 256){
        int n = i >> 4, f = i & 15;
        float v = x[((size_t)(b*NN+n)*FF+f)*TT + t];
        s1 += v*U1[n]; s2 += v*g_u2u3[n];
    }
    __shared__ float r1[256], r2[256];
    r1[tid]=s1; r2[tid]=s2; __syncthreads();
    for (int o=128; o>0; o>>=1){
        if (tid<o){ r1[tid]+=r1[tid+o]; r2[tid]+=r2[tid+o]; }
        __syncthreads();
    }
    if (tid==0){ g_tlhs[b*TT+t]=r1[0]; g_trhs[b*TT+t]=r2[0]; }
}

__global__ void k_E(const float* __restrict__ Ve, const float* __restrict__ be){
    __shared__ float tl[BB*TT], tr[BB*TT], sVe[TT*TT], sbe[TT*TT], Eb[BB*TT*TT];
    int tid = threadIdx.x;
    if (tid < BB*TT){ tl[tid]=g_tlhs[tid]; tr[tid]=g_trhs[tid]; }
    if (tid < TT*TT){ sVe[tid]=Ve[tid]; sbe[tid]=be[tid]; }
    __syncthreads();
    for (int idx = tid; idx < BB*TT*TT; idx += 256){
        int b = idx>>8, t = (idx>>4)&15, r = idx&15;
        float s = 0.f;
        #pragma unroll
        for (int ss=0; ss<TT; ss++)
            s += sVe[t*TT+ss]*sigmoidf_(tl[b*TT+ss]*tr[b*TT+r] + sbe[ss*TT+r]);
        Eb[idx] = s;
    }
    __syncthreads();
    if (tid < BB*TT){
        int base = tid*TT;
        float m = -1e30f;
        for (int r=0;r<TT;r++) m = fmaxf(m, Eb[base+r]);
        float e[TT]; float sum = 0.f;
        for (int r=0;r<TT;r++){ e[r]=expf(Eb[base+r]-m); sum+=e[r]; }
        float inv = 1.f/sum;
        for (int r=0;r<TT;r++) g_E[base+r] = e[r]*inv;
    }
}

// fused: x_TAt + s_lhs + s_rhs (all need the same x row)
__global__ void k_xTAt(const float* __restrict__ x, const float* __restrict__ W1,
                       const float* __restrict__ W2, const float* __restrict__ W3){
    int bn = blockIdx.x;            // b*NN + n
    int b = bn / NN;
    int tid = threadIdx.x;
    __shared__ float xs[256], Es[256], sr0[16];
    xs[tid] = x[(size_t)bn*256 + tid];
    Es[tid] = g_E[b*256 + tid];
    __syncthreads();
    int f = tid >> 4, t = tid & 15;
    float s = 0.f;
    #pragma unroll
    for (int ss=0; ss<TT; ss++) s += Es[t*16+ss]*xs[f*16+ss];
    g_xTAt[(size_t)bn*256 + tid] = s;
    if (tid < 16){
        float a=0.f, c=0.f;
        #pragma unroll
        for (int t2=0;t2<16;t2++){ float v = xs[tid*16+t2]; a += v*W1[t2]; c += v*W3[t2]; }
        g_slhs[bn*16+tid] = a;
        sr0[tid] = c;
    }
    __syncthreads();
    if (tid < 16){
        float g = 0.f;
        #pragma unroll
        for (int kk=0;kk<16;kk++) g += W2[tid*16+kk]*sr0[kk];
        g_srhs[bn*16+tid] = g;
    }
}

__global__ void k_sigP(const float* __restrict__ bs){
    int b = blockIdx.z;
    int m0 = blockIdx.y*32, k0 = blockIdx.x*32;
    int tid = threadIdx.x;
    __shared__ float Lm[32][16], Rk[32][16];
    for (int i = tid; i < 512; i += 256){
        int r = i>>4, c = i&15;
        Lm[r][c] = g_slhs[(b*NN + m0 + r)*16 + c];
        Rk[r][c] = g_srhs[(b*NN + k0 + r)*16 + c];
    }
    __syncthreads();
    for (int e = tid; e < 1024; e += 256){
        int mi = e>>5, ki = e&31;
        float d = bs[(size_t)(m0+mi)*NN + k0 + ki];
        #pragma unroll
        for (int f=0; f<16; f++) d += Lm[mi][f]*Rk[ki][f];
        g_sigP[((size_t)b*NN + m0 + mi)*NN + k0 + ki] = sigmoidf_(d);
    }
}

// ---------------- fp32 SIMT GEMM (128x128x16, 8x8/thread, f32x2 FMAs) ----------------
__device__ __forceinline__ void gemm_body(
    const float* __restrict__ Ag, const float* __restrict__ Bg,
    const float* __restrict__ Dg, float* __restrict__ Cg,
    int M, int Nc, int Kd,
    long long sA, long long sB, long long sD, long long sC,
    float alpha, float beta)
{
    __shared__ float As[16][128];
    __shared__ float Bs[16][128];
    int bz = blockIdx.z;
    const float* A = Ag + bz*sA;
    const float* B = Bg + bz*sB;
    int rowBase = blockIdx.y*128, colBase = blockIdx.x*128;
    int tid = threadIdx.x;
    int tx = tid & 15, ty = tid >> 4;

    unsigned long long acc[8][4];
    #pragma unroll
    for (int i=0;i<8;i++)
        #pragma unroll
        for (int j=0;j<4;j++) acc[i][j] = 0ull;

    int aRow = tid >> 2;           // 0..63
    int aCol = (tid & 3) << 2;     // 0,4,8,12
    int bRow = tid >> 5;           // 0..7
    int bCol = (tid & 31) << 2;    // 0..124

    for (int k0 = 0; k0 < Kd; k0 += 16){
        #pragma unroll
        for (int r=0; r<2; r++){
            int lr = aRow + r*64;
            int grow = rowBase + lr;
            float4 v = make_float4(0.f,0.f,0.f,0.f);
            if (grow < M) v = *(const float4*)(A + (size_t)grow*Kd + k0 + aCol);
            As[aCol+0][lr]=v.x; As[aCol+1][lr]=v.y; As[aCol+2][lr]=v.z; As[aCol+3][lr]=v.w;
        }
        #pragma unroll
        for (int r=0; r<2; r++){
            int lr = bRow + r*8;
            int gcol = colBase + bCol;
            float4 v = make_float4(0.f,0.f,0.f,0.f);
            if (gcol < Nc) v = *(const float4*)(B + (size_t)(k0+lr)*Nc + gcol);
            *(float4*)&Bs[lr][bCol] = v;
        }
        __syncthreads();
        #pragma unroll
        for (int k=0; k<16; k++){
            float4 a0 = *(const float4*)&As[k][ty*8];
            float4 a1 = *(const float4*)&As[k][ty*8+4];
            unsigned long long av[8];
            av[0]=pack2(a0.x,a0.x); av[1]=pack2(a0.y,a0.y);
            av[2]=pack2(a0.z,a0.z); av[3]=pack2(a0.w,a0.w);
            av[4]=pack2(a1.x,a1.x); av[5]=pack2(a1.y,a1.y);
            av[6]=pack2(a1.z,a1.z); av[7]=pack2(a1.w,a1.w);
            unsigned long long bv[4];
            const unsigned long long* bp = (const unsigned long long*)&Bs[k][tx*8];
            bv[0]=bp[0]; bv[1]=bp[1]; bv[2]=bp[2]; bv[3]=bp[3];
            #pragma unroll
            for (int i=0;i<8;i++)
                #pragma unroll
                for (int j=0;j<4;j++) fma2(acc[i][j], av[i], bv[j]);
        }
        __syncthreads();
    }

    const float* D = Dg ? Dg + bz*sD : (const float*)0;
    float* C = Cg + bz*sC;
    #pragma unroll
    for (int i=0;i<8;i++){
        int grow = rowBase + ty*8 + i;
        if (grow >= M) continue;
        #pragma unroll
        for (int j=0;j<4;j++){
            float2 v = unpack2(acc[i][j]);
            int gc = colBase + tx*8 + j*2;
            if (gc < Nc){
                float r0 = alpha*v.x;
                if (D) r0 += beta*D[(size_t)grow*Nc + gc];
                C[(size_t)grow*Nc + gc] = r0;
            }
            if (gc+1 < Nc){
                float r1 = alpha*v.y;
                if (D) r1 += beta*D[(size_t)grow*Nc + gc + 1];
                C[(size_t)grow*Nc + gc + 1] = r1;
            }
        }
    }
}

__global__ void __launch_bounds__(256,2) gemm_S(const float* __restrict__ Vs){
    gemm_body(Vs, g_sigP, (const float*)0, g_S, NN, NN, NN,
              0LL, (long long)NN*NN, 0LL, (long long)NN*NN, 1.f, 0.f);
}
__global__ void __launch_bounds__(256,2) gemm_xSAtt(){
    gemm_body(g_S, g_xTAt, (const float*)0, g_Tx0, NN, 256, NN,
              (long long)NN*NN, (long long)NN*256, 0LL, (long long)NN*256, 1.f, 0.f);
}
__global__ void __launch_bounds__(256,2) gemm_Tx1(const float* __restrict__ lap){
    gemm_body(lap, g_Tx0, (const float*)0, g_Tx1, NN, 256, NN,
              0LL, (long long)NN*256, 0LL, (long long)NN*256, 1.f, 0.f);
}
__global__ void __launch_bounds__(256,2) gemm_Tx2(const float* __restrict__ lap){
    gemm_body(lap, g_Tx1, g_Tx0, g_Tx2, NN, 256, NN,
              0LL, (long long)NN*256, (long long)NN*256, (long long)NN*256, 2.f, -1.f);
}

// ---------------- softmax over last dim of S (rows of 4000) ----------------
__global__ void k_softmax(){
    __shared__ float row[NN];
    __shared__ float red[256];
    int tid = threadIdx.x;
    size_t base = (size_t)blockIdx.x * NN;
    float m = -1e30f;
    for (int i = tid; i < NN; i += 256){ float v = g_S[base+i]; row[i]=v; m = fmaxf(m,v); }
    red[tid]=m; __syncthreads();
    for (int o=128;o>0;o>>=1){ if (tid<o) red[tid]=fmaxf(red[tid],red[tid+o]); __syncthreads(); }
    m = red[0]; __syncthreads();
    float s = 0.f;
    for (int i = tid; i < NN; i += 256){ float e = expf(row[i]-m); row[i]=e; s += e; }
    red[tid]=s; __syncthreads();
    for (int o=128;o>0;o>>=1){ if (tid<o) red[tid]+=red[tid+o]; __syncthreads(); }
    float inv = 1.f/red[0];
    for (int i = tid; i < NN; i += 256) g_S[base+i] = row[i]*inv;
}

// ---------------- cheb combine + time conv + residual -> y ----------------
__global__ void k_final(const float* __restrict__ x, const float* __restrict__ cheb,
                        const float* __restrict__ tw, const float* __restrict__ tb){
    int bn = blockIdx.x;
    int tid = threadIdx.x;
    __shared__ float xs[256], t0[256], t1[256], t2[256], ts0[16], ts1[16], ts2[16];
    size_t rb = (size_t)bn*256;
    xs[tid]=x[rb+tid]; t0[tid]=g_Tx0[rb+tid]; t1[tid]=g_Tx1[rb+tid]; t2[tid]=g_Tx2[rb+tid];
    __syncthreads();
    if (tid < 48){
        int kk = tid>>4, f = tid&15;
        const float* src = (kk==0) ? t0 : ((kk==1) ? t1 : t2);
        float s = 0.f;
        #pragma unroll
        for (int t=0;t<16;t++) s += src[f*16+t];
        float* dst = (kk==0) ? ts0 : ((kk==1) ? ts1 : ts2);
        dst[f] = s;
    }
    __syncthreads();
    if (tid < 16){
        int o = tid;
        float tm = 0.f;
        #pragma unroll
        for (int c=0;c<16;c++)
            #pragma unroll
            for (int t=0;t<16;t++) tm += xs[c*16+t]*tw[(o*16+c)*16+t];
        float sp = 0.f;
        #pragma unroll
        for (int f=0;f<16;f++)
            sp += ts0[f]*cheb[f*16+o] + ts1[f]*cheb[256+f*16+o] + ts2[f]*cheb[512+f*16+o];
        g_y[bn*16+o] = sp*(1.f/16.f) + tm + tb[o] + xs[o*16+15];
    }
}

// ---------------- layernorm stats (per batch, deterministic) ----------------
__global__ void k_stats(){
    int b = blockIdx.x, tid = threadIdx.x;
    double s = 0.0, ss = 0.0;
    for (int i = tid; i < NN*OO; i += 256){
        float v = g_y[b*NN*OO + i];
        s += (double)v; ss += (double)v*(double)v;
    }
    __shared__ double rs[256], rq[256];
    rs[tid]=s; rq[tid]=ss; __syncthreads();
    for (int o=128;o>0;o>>=1){ if (tid<o){ rs[tid]+=rs[tid+o]; rq[tid]+=rq[tid+o]; } __syncthreads(); }
    if (tid==0){
        double mean = rs[0]/(double)(NN*OO);
        double var  = rq[0]/(double)(NN*OO) - mean*mean;
        g_stats[b*2]   = (float)mean;
        g_stats[b*2+1] = (float)(1.0/sqrt(var + 1e-5));
    }
}

__global__ void k_out(const float* __restrict__ lng, const float* __restrict__ lnb,
                      float* __restrict__ out){
    int i = blockIdx.x*256 + threadIdx.x;
    if (i < BB*NN*OO){
        int b  = i / (NN*OO);
        int no = i % (NN*OO);
        float v = (g_y[i]-g_stats[b*2])*g_stats[b*2+1]*lng[no] + lnb[no];
        out[i] = fmaxf(v, 0.f);
    }
}

// ---------------- launcher ----------------
extern "C" void kernel_launch(void* const* d_in, const int* in_sizes, int n_in,
                              void* d_out, int out_size){
    const float* x    = (const float*)d_in[0];
    const float* lap  = (const float*)d_in[1];
    const float* W1   = (const float*)d_in[2];
    const float* W2   = (const float*)d_in[3];
    const float* W3   = (const float*)d_in[4];
    const float* bs   = (const float*)d_in[5];
    const float* Vs   = (const float*)d_in[6];
    const float* U1   = (const float*)d_in[7];
    const float* U2   = (const float*)d_in[8];
    const float* U3   = (const float*)d_in[9];
    const float* be   = (const float*)d_in[10];
    const float* Ve   = (const float*)d_in[11];
    const float* cheb = (const float*)d_in[12];
    const float* tw   = (const float*)d_in[13];
    const float* tb   = (const float*)d_in[14];
    const float* lng  = (const float*)d_in[15];
    const float* lnb  = (const float*)d_in[16];
    float* out = (float*)d_out;

    k_u2u3<<<(NN+255)/256, 256>>>(U2, U3);
    k_tred<<<BB*TT, 256>>>(x, U1);
    k_E<<<1, 256>>>(Ve, be);
    k_xTAt<<<BB*NN, 256>>>(x, W1, W2, W3);
    k_sigP<<<dim3(125,125,BB), 256>>>(bs);
    gemm_S<<<dim3(32,32,BB), 256>>>(Vs);
    k_softmax<<<BB*NN, 256>>>();
    gemm_xSAtt<<<dim3(2,32,BB), 256>>>();
    gemm_Tx1<<<dim3(2,32,BB), 256>>>(lap);
    gemm_Tx2<<<dim3(2,32,BB), 256>>>(lap);
    k_final<<<BB*NN, 256>>>(x, cheb, tw, tb);
    k_stats<<<BB, 256>>>();
    k_out<<<(BB*NN*OO+255)/256, 256>>>(lng, lnb, out);
}

// round 3
// speedup vs baseline: 1.0002x; 1.0002x over previous
#include <cuda_runtime.h>
#include <math.h>

#define NN 4000
#define BB 4
#define FF 16
#define TT 16
#define OO 16

// ---------------- scratch (device globals; no allocation allowed) ----------------
__device__ float g_u2u3[NN];
__device__ float g_tlhs[BB*TT];
__device__ float g_trhs[BB*TT];
__device__ float g_E[BB*TT*TT];
__device__ float g_xTAt[BB*NN*FF*TT];
__device__ float g_slhs[BB*NN*FF];
__device__ float g_srhs[BB*NN*FF];
__device__ float g_sigP[64000000];   // [B][N][N] 256MB
__device__ float g_S[64000000];      // [B][N][N] 256MB
__device__ float g_Tx0[BB*NN*FF*TT];
__device__ float g_Tx1[BB*NN*FF*TT];
__device__ float g_Tx2[BB*NN*FF*TT];
__device__ float g_y[BB*NN*OO];
__device__ float g_stats[BB*2];

__device__ __forceinline__ float sigmoidf_(float v){ return 1.f/(1.f+expf(-v)); }

// ---------------- packed f32x2 helpers (Blackwell full-rate fp32) ----------------
__device__ __forceinline__ unsigned long long pack2(float x, float y){
    unsigned long long r;
    asm("mov.b64 %0, {%1, %2};" : "=l"(r) : "f"(x), "f"(y));
    return r;
}
__device__ __forceinline__ void fma2(unsigned long long &d, unsigned long long a, unsigned long long b){
    asm("fma.rn.f32x2 %0, %1, %2, %0;" : "+l"(d) : "l"(a), "l"(b));
}
__device__ __forceinline__ float2 unpack2(unsigned long long v){
    float2 f; asm("mov.b64 {%0, %1}, %2;" : "=f"(f.x), "=f"(f.y) : "l"(v)); return f;
}

// ---------------- small kernels ----------------
__global__ void k_u2u3(const float* __restrict__ U2, const float* __restrict__ U3){
    int n = blockIdx.x*blockDim.x + threadIdx.x;
    if (n < NN){
        float s = 0.f;
        #pragma unroll
        for (int g=0; g<FF; g++) s += U2[g*NN+n]*U3[g];
        g_u2u3[n] = s;
    }
}

__global__ void k_tred(const float* __restrict__ x, const float* __restrict__ U1){
    int b = blockIdx.x >> 4, t = blockIdx.x & 15;
    int tid = threadIdx.x;
    float s1 = 0.f, s2 = 0.f;
    for (int i = tid; i < NN*FF; i += 256){
        int n = i >> 4, f = i & 15;
        float v = x[((size_t)(b*NN+n)*FF+f)*TT + t];
        s1 += v*U1[n]; s2 += v*g_u2u3[n];
    }
    __shared__ float r1[256], r2[256];
    r1[tid]=s1; r2[tid]=s2; __syncthreads();
    for (int o=128; o>0; o>>=1){
        if (tid<o){ r1[tid]+=r1[tid+o]; r2[tid]+=r2[tid+o]; }
        __syncthreads();
    }
    if (tid==0){ g_tlhs[b*TT+t]=r1[0]; g_trhs[b*TT+t]=r2[0]; }
}

__global__ void k_E(const float* __restrict__ Ve, const float* __restrict__ be){
    __shared__ float tl[BB*TT], tr[BB*TT], sVe[TT*TT], sbe[TT*TT], Eb[BB*TT*TT];
    int tid = threadIdx.x;
    if (tid < BB*TT){ tl[tid]=g_tlhs[tid]; tr[tid]=g_trhs[tid]; }
    if (tid < TT*TT){ sVe[tid]=Ve[tid]; sbe[tid]=be[tid]; }
    __syncthreads();
    for (int idx = tid; idx < BB*TT*TT; idx += 256){
        int b = idx>>8, t = (idx>>4)&15, r = idx&15;
        float s = 0.f;
        #pragma unroll
        for (int ss=0; ss<TT; ss++)
            s += sVe[t*TT+ss]*sigmoidf_(tl[b*TT+ss]*tr[b*TT+r] + sbe[ss*TT+r]);
        Eb[idx] = s;
    }
    __syncthreads();
    if (tid < BB*TT){
        int base = tid*TT;
        float m = -1e30f;
        for (int r=0;r<TT;r++) m = fmaxf(m, Eb[base+r]);
        float e[TT]; float sum = 0.f;
        for (int r=0;r<TT;r++){ e[r]=expf(Eb[base+r]-m); sum+=e[r]; }
        float inv = 1.f/sum;
        for (int r=0;r<TT;r++) g_E[base+r] = e[r]*inv;
    }
}

// fused: x_TAt + s_lhs + s_rhs (all need the same x row)
__global__ void k_xTAt(const float* __restrict__ x, const float* __restrict__ W1,
                       const float* __restrict__ W2, const float* __restrict__ W3){
    int bn = blockIdx.x;            // b*NN + n
    int b = bn / NN;
    int tid = threadIdx.x;
    __shared__ float xs[256], Es[256], sr0[16];
    xs[tid] = x[(size_t)bn*256 + tid];
    Es[tid] = g_E[b*256 + tid];
    __syncthreads();
    int f = tid >> 4, t = tid & 15;
    float s = 0.f;
    #pragma unroll
    for (int ss=0; ss<TT; ss++) s += Es[t*16+ss]*xs[f*16+ss];
    g_xTAt[(size_t)bn*256 + tid] = s;
    if (tid < 16){
        float a=0.f, c=0.f;
        #pragma unroll
        for (int t2=0;t2<16;t2++){ float v = xs[tid*16+t2]; a += v*W1[t2]; c += v*W3[t2]; }
        g_slhs[bn*16+tid] = a;
        sr0[tid] = c;
    }
    __syncthreads();
    if (tid < 16){
        float g = 0.f;
        #pragma unroll
        for (int kk=0;kk<16;kk++) g += W2[tid*16+kk]*sr0[kk];
        g_srhs[bn*16+tid] = g;
    }
}

__global__ void k_sigP(const float* __restrict__ bs){
    int b = blockIdx.z;
    int m0 = blockIdx.y*32, k0 = blockIdx.x*32;
    int tid = threadIdx.x;
    __shared__ float Lm[32][16], Rk[32][16];
    for (int i = tid; i < 512; i += 256){
        int r = i>>4, c = i&15;
        Lm[r][c] = g_slhs[(b*NN + m0 + r)*16 + c];
        Rk[r][c] = g_srhs[(b*NN + k0 + r)*16 + c];
    }
    __syncthreads();
    for (int e = tid; e < 1024; e += 256){
        int mi = e>>5, ki = e&31;
        float d = bs[(size_t)(m0+mi)*NN + k0 + ki];
        #pragma unroll
        for (int f=0; f<16; f++) d += Lm[mi][f]*Rk[ki][f];
        g_sigP[((size_t)b*NN + m0 + mi)*NN + k0 + ki] = sigmoidf_(d);
    }
}

// ---------------- fp32 SIMT GEMM (128x128x16, 8x8/thread, f32x2 FMAs) ----------------
__device__ __forceinline__ void gemm_body(
    const float* __restrict__ Ag, const float* __restrict__ Bg,
    const float* __restrict__ Dg, float* __restrict__ Cg,
    int M, int Nc, int Kd,
    long long sA, long long sB, long long sD, long long sC,
    float alpha, float beta)
{
    __shared__ float As[16][128];
    __shared__ float Bs[16][128];
    int bz = blockIdx.z;
    const float* A = Ag + bz*sA;
    const float* B = Bg + bz*sB;
    int rowBase = blockIdx.y*128, colBase = blockIdx.x*128;
    int tid = threadIdx.x;
    int tx = tid & 15, ty = tid >> 4;

    unsigned long long acc[8][4];
    #pragma unroll
    for (int i=0;i<8;i++)
        #pragma unroll
        for (int j=0;j<4;j++) acc[i][j] = 0ull;

    int aRow = tid >> 2;           // 0..63
    int aCol = (tid & 3) << 2;     // 0,4,8,12
    int bRow = tid >> 5;           // 0..7
    int bCol = (tid & 31) << 2;    // 0..124

    for (int k0 = 0; k0 < Kd; k0 += 16){
        #pragma unroll
        for (int r=0; r<2; r++){
            int lr = aRow + r*64;
            int grow = rowBase + lr;
            float4 v = make_float4(0.f,0.f,0.f,0.f);
            if (grow < M) v = *(const float4*)(A + (size_t)grow*Kd + k0 + aCol);
            As[aCol+0][lr]=v.x; As[aCol+1][lr]=v.y; As[aCol+2][lr]=v.z; As[aCol+3][lr]=v.w;
        }
        #pragma unroll
        for (int r=0; r<2; r++){
            int lr = bRow + r*8;
            int gcol = colBase + bCol;
            float4 v = make_float4(0.f,0.f,0.f,0.f);
            if (gcol < Nc) v = *(const float4*)(B + (size_t)(k0+lr)*Nc + gcol);
            *(float4*)&Bs[lr][bCol] = v;
        }
        __syncthreads();
        #pragma unroll
        for (int k=0; k<16; k++){
            float4 a0 = *(const float4*)&As[k][ty*8];
            float4 a1 = *(const float4*)&As[k][ty*8+4];
            unsigned long long av[8];
            av[0]=pack2(a0.x,a0.x); av[1]=pack2(a0.y,a0.y);
            av[2]=pack2(a0.z,a0.z); av[3]=pack2(a0.w,a0.w);
            av[4]=pack2(a1.x,a1.x); av[5]=pack2(a1.y,a1.y);
            av[6]=pack2(a1.z,a1.z); av[7]=pack2(a1.w,a1.w);
            unsigned long long bv[4];
            const unsigned long long* bp = (const unsigned long long*)&Bs[k][tx*8];
            bv[0]=bp[0]; bv[1]=bp[1]; bv[2]=bp[2]; bv[3]=bp[3];
            #pragma unroll
            for (int i=0;i<8;i++)
                #pragma unroll
                for (int j=0;j<4;j++) fma2(acc[i][j], av[i], bv[j]);
        }
        __syncthreads();
    }

    const float* D = Dg ? Dg + bz*sD : (const float*)0;
    float* C = Cg + bz*sC;
    #pragma unroll
    for (int i=0;i<8;i++){
        int grow = rowBase + ty*8 + i;
        if (grow >= M) continue;
        #pragma unroll
        for (int j=0;j<4;j++){
            float2 v = unpack2(acc[i][j]);
            int gc = colBase + tx*8 + j*2;
            if (gc < Nc){
                float r0 = alpha*v.x;
                if (D) r0 += beta*D[(size_t)grow*Nc + gc];
                C[(size_t)grow*Nc + gc] = r0;
            }
            if (gc+1 < Nc){
                float r1 = alpha*v.y;
                if (D) r1 += beta*D[(size_t)grow*Nc + gc + 1];
                C[(size_t)grow*Nc + gc + 1] = r1;
            }
        }
    }
}

__global__ void __launch_bounds__(256,2) gemm_S(const float* __restrict__ Vs){
    gemm_body(Vs, g_sigP, (const float*)0, g_S, NN, NN, NN,
              0LL, (long long)NN*NN, 0LL, (long long)NN*NN, 1.f, 0.f);
}
__global__ void __launch_bounds__(256,2) gemm_xSAtt(){
    gemm_body(g_S, g_xTAt, (const float*)0, g_Tx0, NN, 256, NN,
              (long long)NN*NN, (long long)NN*256, 0LL, (long long)NN*256, 1.f, 0.f);
}
__global__ void __launch_bounds__(256,2) gemm_Tx1(const float* __restrict__ lap){
    gemm_body(lap, g_Tx0, (const float*)0, g_Tx1, NN, 256, NN,
              0LL, (long long)NN*256, 0LL, (long long)NN*256, 1.f, 0.f);
}
__global__ void __launch_bounds__(256,2) gemm_Tx2(const float* __restrict__ lap){
    gemm_body(lap, g_Tx1, g_Tx0, g_Tx2, NN, 256, NN,
              0LL, (long long)NN*256, (long long)NN*256, (long long)NN*256, 2.f, -1.f);
}

// ---------------- softmax over last dim of S (rows of 4000) ----------------
__global__ void k_softmax(){
    __shared__ float row[NN];
    __shared__ float red[256];
    int tid = threadIdx.x;
    size_t base = (size_t)blockIdx.x * NN;
    float m = -1e30f;
    for (int i = tid; i < NN; i += 256){ float v = g_S[base+i]; row[i]=v; m = fmaxf(m,v); }
    red[tid]=m; __syncthreads();
    for (int o=128;o>0;o>>=1){ if (tid<o) red[tid]=fmaxf(red[tid],red[tid+o]); __syncthreads(); }
    m = red[0]; __syncthreads();
    float s = 0.f;
    for (int i = tid; i < NN; i += 256){ float e = expf(row[i]-m); row[i]=e; s += e; }
    red[tid]=s; __syncthreads();
    for (int o=128;o>0;o>>=1){ if (tid<o) red[tid]+=red[tid+o]; __syncthreads(); }
    float inv = 1.f/red[0];
    for (int i = tid; i < NN; i += 256) g_S[base+i] = row[i]*inv;
}

// ---------------- cheb combine + time conv + residual -> y ----------------
__global__ void k_final(const float* __restrict__ x, const float* __restrict__ cheb,
                        const float* __restrict__ tw, const float* __restrict__ tb){
    int bn = blockIdx.x;
    int tid = threadIdx.x;
    __shared__ float xs[256], t0[256], t1[256], t2[256], ts0[16], ts1[16], ts2[16];
    size_t rb = (size_t)bn*256;
    xs[tid]=x[rb+tid]; t0[tid]=g_Tx0[rb+tid]; t1[tid]=g_Tx1[rb+tid]; t2[tid]=g_Tx2[rb+tid];
    __syncthreads();
    if (tid < 48){
        int kk = tid>>4, f = tid&15;
        const float* src = (kk==0) ? t0 : ((kk==1) ? t1 : t2);
        float s = 0.f;
        #pragma unroll
        for (int t=0;t<16;t++) s += src[f*16+t];
        float* dst = (kk==0) ? ts0 : ((kk==1) ? ts1 : ts2);
        dst[f] = s;
    }
    __syncthreads();
    if (tid < 16){
        int o = tid;
        float tm = 0.f;
        #pragma unroll
        for (int c=0;c<16;c++)
            #pragma unroll
            for (int t=0;t<16;t++) tm += xs[c*16+t]*tw[(o*16+c)*16+t];
        float sp = 0.f;
        #pragma unroll
        for (int f=0;f<16;f++)
            sp += ts0[f]*cheb[f*16+o] + ts1[f]*cheb[256+f*16+o] + ts2[f]*cheb[512+f*16+o];
        g_y[bn*16+o] = sp*(1.f/16.f) + tm + tb[o] + xs[o*16+15];
    }
}

// ---------------- layernorm stats (per batch, deterministic) ----------------
__global__ void k_stats(){
    int b = blockIdx.x, tid = threadIdx.x;
    double s = 0.0, ss = 0.0;
    for (int i = tid; i < NN*OO; i += 256){
        float v = g_y[b*NN*OO + i];
        s += (double)v; ss += (double)v*(double)v;
    }
    __shared__ double rs[256], rq[256];
    rs[tid]=s; rq[tid]=ss; __syncthreads();
    for (int o=128;o>0;o>>=1){ if (tid<o){ rs[tid]+=rs[tid+o]; rq[tid]+=rq[tid+o]; } __syncthreads(); }
    if (tid==0){
        double mean = rs[0]/(double)(NN*OO);
        double var  = rq[0]/(double)(NN*OO) - mean*mean;
        g_stats[b*2]   = (float)mean;
        g_stats[b*2+1] = (float)(1.0/sqrt(var + 1e-5));
    }
}

__global__ void k_out(const float* __restrict__ lng, const float* __restrict__ lnb,
                      float* __restrict__ out){
    int i = blockIdx.x*256 + threadIdx.x;
    if (i < BB*NN*OO){
        int b  = i / (NN*OO);
        int no = i % (NN*OO);
        float v = (g_y[i]-g_stats[b*2])*g_stats[b*2+1]*lng[no] + lnb[no];
        out[i] = fmaxf(v, 0.f);
    }
}

// ---------------- launcher ----------------
extern "C" void kernel_launch(void* const* d_in, const int* in_sizes, int n_in,
                              void* d_out, int out_size){
    const float* x    = (const float*)d_in[0];
    const float* lap  = (const float*)d_in[1];
    const float* W1   = (const float*)d_in[2];
    const float* W2   = (const float*)d_in[3];
    const float* W3   = (const float*)d_in[4];
    const float* bs   = (const float*)d_in[5];
    const float* Vs   = (const float*)d_in[6];
    const float* U1   = (const float*)d_in[7];
    const float* U2   = (const float*)d_in[8];
    const float* U3   = (const float*)d_in[9];
    const float* be   = (const float*)d_in[10];
    const float* Ve   = (const float*)d_in[11];
    const float* cheb = (const float*)d_in[12];
    const float* tw   = (const float*)d_in[13];
    const float* tb   = (const float*)d_in[14];
    const float* lng  = (const float*)d_in[15];
    const float* lnb  = (const float*)d_in[16];
    float* out = (float*)d_out;

    k_u2u3<<<(NN+255)/256, 256>>>(U2, U3);
    k_tred<<<BB*TT, 256>>>(x, U1);
    k_E<<<1, 256>>>(Ve, be);
    k_xTAt<<<BB*NN, 256>>>(x, W1, W2, W3);
    k_sigP<<<dim3(125,125,BB), 256>>>(bs);
    gemm_S<<<dim3(32,32,BB), 256>>>(Vs);
    k_softmax<<<BB*NN, 256>>>();
    gemm_xSAtt<<<dim3(2,32,BB), 256>>>();
    gemm_Tx1<<<dim3(2,32,BB), 256>>>(lap);
    gemm_Tx2<<<dim3(2,32,BB), 256>>>(lap);
    k_final<<<BB*NN, 256>>>(x, cheb, tw, tb);
    k_stats<<<BB, 256>>>();
    k_out<<<(BB*NN*OO+255)/256, 256>>>(lng, lnb, out);
}

// round 5
// speedup vs baseline: 2.0069x; 2.0065x over previous
#include <cuda_runtime.h>
#include <cuda_bf16.h>
#include <math.h>
#include <stdint.h>

#define NN 4000
#define BB 4
#define FF 16
#define TT 16
#define OO 16

__device__ float g_u2u3[NN];
__device__ float g_tlhs[BB*TT];
__device__ float g_trhs[BB*TT];
__device__ float g_E[BB*TT*TT];
__device__ float g_xTAt[BB*NN*FF*TT];
__device__ float g_slhs[BB*NN*FF];
__device__ float g_srhs[BB*NN*FF];
__device__ __align__(256) __nv_bfloat16 g_vs_h[(size_t)NN*NN];
__device__ __align__(256) __nv_bfloat16 g_vs_l[(size_t)NN*NN];
__device__ __align__(256) __nv_bfloat16 g_spT_h[(size_t)BB*NN*NN]; // [b][k][m] centered sigmoid hi
__device__ __align__(256) __nv_bfloat16 g_spT_l[(size_t)BB*NN*NN]; // lo
__device__ __align__(256) float g_S[(size_t)BB*NN*NN];
__device__ float g_Tx0[BB*NN*FF*TT];
__device__ float g_Tx1[BB*NN*FF*TT];
__device__ float g_Tx2[BB*NN*FF*TT];
__device__ float g_y[BB*NN*OO];
__device__ float g_stats[BB*2];

__device__ __forceinline__ float sigmoidf_(float v){ return 1.f/(1.f+expf(-v)); }

__device__ __forceinline__ unsigned long long pack2(float x, float y){
    unsigned long long r; asm("mov.b64 %0, {%1, %2};" : "=l"(r) : "f"(x), "f"(y)); return r;
}
__device__ __forceinline__ void fma2(unsigned long long &d, unsigned long long a, unsigned long long b){
    asm("fma.rn.f32x2 %0, %1, %2, %0;" : "+l"(d) : "l"(a), "l"(b));
}
__device__ __forceinline__ float2 unpack2(unsigned long long v){
    float2 f; asm("mov.b64 {%0, %1}, %2;" : "=f"(f.x), "=f"(f.y) : "l"(v)); return f;
}

// ---- ptx helpers (all sm_80-generic: cp.async, ldmatrix, mma.sync) ----
__device__ __forceinline__ uint32_t smem_u32(const void* p){
    uint32_t a;
    asm("{ .reg .u64 t; cvta.to.shared.u64 t, %1; cvt.u32.u64 %0, t; }" : "=r"(a) : "l"(p));
    return a;
}
#define SWZ(o) ((uint32_t)(o) ^ ((((uint32_t)(o)) >> 3) & 0x70u))
__device__ __forceinline__ void cpa16(uint32_t dst, const void* src, bool p){
    int sz = p ? 16 : 0;
    asm volatile("cp.async.cg.shared.global [%0], [%1], 16, %2;" :: "r"(dst), "l"(src), "r"(sz) : "memory");
}
__device__ __forceinline__ void cpa_commit(){ asm volatile("cp.async.commit_group;" ::: "memory"); }
__device__ __forceinline__ void ldsm4(uint32_t* r, uint32_t addr){
    asm volatile("ldmatrix.sync.aligned.m8n8.x4.shared.b16 {%0,%1,%2,%3}, [%4];"
        : "=r"(r[0]),"=r"(r[1]),"=r"(r[2]),"=r"(r[3]) : "r"(addr));
}
__device__ __forceinline__ void ldsm2(uint32_t* r, uint32_t addr){
    asm volatile("ldmatrix.sync.aligned.m8n8.x2.shared.b16 {%0,%1}, [%2];"
        : "=r"(r[0]),"=r"(r[1]) : "r"(addr));
}
__device__ __forceinline__ void mma16816(float* c, const uint32_t* a, const uint32_t* b){
    asm volatile("mma.sync.aligned.m16n8k16.row.col.f32.bf16.bf16.f32 "
        "{%0,%1,%2,%3}, {%4,%5,%6,%7}, {%8,%9}, {%0,%1,%2,%3};"
        : "+f"(c[0]),"+f"(c[1]),"+f"(c[2]),"+f"(c[3])
        : "r"(a[0]),"r"(a[1]),"r"(a[2]),"r"(a[3]), "r"(b[0]),"r"(b[1]));
}

// ---- small kernels ----
__global__ void k_u2u3(const float* __restrict__ U2, const float* __restrict__ U3){
    int n = blockIdx.x*blockDim.x + threadIdx.x;
    if (n < NN){
        float s = 0.f;
        #pragma unroll
        for (int g=0; g<FF; g++) s += U2[g*NN+n]*U3[g];
        g_u2u3[n] = s;
    }
}
__global__ void k_tred(const float* __restrict__ x, const float* __restrict__ U1){
    int b = blockIdx.x >> 4, t = blockIdx.x & 15;
    int tid = threadIdx.x;
    float s1 = 0.f, s2 = 0.f;
    for (int i = tid; i < NN*FF; i += 256){
        int n = i >> 4, f = i & 15;
        float v = x[((size_t)(b*NN+n)*FF+f)*TT + t];
        s1 += v*U1[n]; s2 += v*g_u2u3[n];
    }
    __shared__ float r1[256], r2[256];
    r1[tid]=s1; r2[tid]=s2; __syncthreads();
    for (int o=128; o>0; o>>=1){
        if (tid<o){ r1[tid]+=r1[tid+o]; r2[tid]+=r2[tid+o]; }
        __syncthreads();
    }
    if (tid==0){ g_tlhs[b*TT+t]=r1[0]; g_trhs[b*TT+t]=r2[0]; }
}
__global__ void k_E(const float* __restrict__ Ve, const float* __restrict__ be){
    __shared__ float tl[BB*TT], tr[BB*TT], sVe[TT*TT], sbe[TT*TT], Eb[BB*TT*TT];
    int tid = threadIdx.x;
    if (tid < BB*TT){ tl[tid]=g_tlhs[tid]; tr[tid]=g_trhs[tid]; }
    if (tid < TT*TT){ sVe[tid]=Ve[tid]; sbe[tid]=be[tid]; }
    __syncthreads();
    for (int idx = tid; idx < BB*TT*TT; idx += 256){
        int b = idx>>8, t = (idx>>4)&15, r = idx&15;
        float s = 0.f;
        #pragma unroll
        for (int ss=0; ss<TT; ss++)
            s += sVe[t*TT+ss]*sigmoidf_(tl[b*TT+ss]*tr[b*TT+r] + sbe[ss*TT+r]);
        Eb[idx] = s;
    }
    __syncthreads();
    if (tid < BB*TT){
        int base = tid*TT;
        float m = -1e30f;
        for (int r=0;r<TT;r++) m = fmaxf(m, Eb[base+r]);
        float e[TT]; float sum = 0.f;
        for (int r=0;r<TT;r++){ e[r]=expf(Eb[base+r]-m); sum+=e[r]; }
        float inv = 1.f/sum;
        for (int r=0;r<TT;r++) g_E[base+r] = e[r]*inv;
    }
}
__global__ void k_xTAt(const float* __restrict__ x, const float* __restrict__ W1,
                       const float* __restrict__ W2, const float* __restrict__ W3){
    int bn = blockIdx.x;
    int b = bn / NN;
    int tid = threadIdx.x;
    __shared__ float xs[256], Es[256], sr0[16];
    xs[tid] = x[(size_t)bn*256 + tid];
    Es[tid] = g_E[b*256 + tid];
    __syncthreads();
    int f = tid >> 4, t = tid & 15;
    float s = 0.f;
    #pragma unroll
    for (int ss=0; ss<TT; ss++) s += Es[t*16+ss]*xs[f*16+ss];
    g_xTAt[(size_t)bn*256 + tid] = s;
    if (tid < 16){
        float a=0.f, c=0.f;
        #pragma unroll
        for (int t2=0;t2<16;t2++){ float v = xs[tid*16+t2]; a += v*W1[t2]; c += v*W3[t2]; }
        g_slhs[bn*16+tid] = a;
        sr0[tid] = c;
    }
    __syncthreads();
    if (tid < 16){
        float g = 0.f;
        #pragma unroll
        for (int kk=0;kk<16;kk++) g += W2[tid*16+kk]*sr0[kk];
        g_srhs[bn*16+tid] = g;
    }
}
__global__ void k_vs_split(const float* __restrict__ Vs){
    size_t i = (size_t)blockIdx.x*256 + threadIdx.x;
    if (i < (size_t)NN*NN){
        float v = Vs[i];
        __nv_bfloat16 h = __float2bfloat16(v);
        g_vs_h[i] = h;
        g_vs_l[i] = __float2bfloat16(v - __bfloat162float(h));
    }
}
// sigmoid(prod+bs) - 0.5 (softmax shift-invariance), transposed [b][k][m], bf16 hi/lo
__global__ void k_sigP(const float* __restrict__ bs){
    int b = blockIdx.z;
    int m0 = blockIdx.y*32, k0 = blockIdx.x*32;
    int tid = threadIdx.x;
    __shared__ float Lm[32][17], Rk[32][17], sbs[32][33];
    for (int i = tid; i < 512; i += 256){
        int r = i>>4, c = i&15;
        Lm[r][c] = g_slhs[(b*NN + m0 + r)*16 + c];
        Rk[r][c] = g_srhs[(b*NN + k0 + r)*16 + c];
    }
    for (int i = tid; i < 1024; i += 256){
        int mi = i>>5, ki = i&31;
        sbs[mi][ki] = bs[(size_t)(m0+mi)*NN + k0 + ki];
    }
    __syncthreads();
    for (int e = tid; e < 1024; e += 256){
        int ki = e>>5, mi = e&31;
        float d = sbs[mi][ki];
        #pragma unroll
        for (int f=0; f<16; f++) d += Lm[mi][f]*Rk[ki][f];
        float s = sigmoidf_(d) - 0.5f;
        __nv_bfloat16 h = __float2bfloat16(s);
        size_t o = (size_t)b*NN*NN + (size_t)(k0+ki)*NN + (m0+mi);
        g_spT_h[o] = h;
        g_spT_l[o] = __float2bfloat16(s - __bfloat162float(h));
    }
}

// ---- bf16-split tensor GEMM via mma.sync: S'[b,n,k] = sum_m Vs[n,m]*(sigP[b,m,k]-0.5) ----
#define KCHUNK 64
#define NSTAGE 3
#define STG_BYTES 65536
#define OFF_AH 0
#define OFF_AL 16384
#define OFF_BH 32768
#define OFF_BL 49152
#define NCHUNK 63
#define SMEM_REQ (NSTAGE*STG_BYTES + 1024)

__global__ void __launch_bounds__(256,1) gemm_S_mma(){
    extern __shared__ char dsm[];
    uint32_t sb = (smem_u32(dsm) + 1023u) & ~1023u;
    int tid = threadIdx.x, lane = tid&31, wid = tid>>5;
    int b = blockIdx.z;
    int mBase = blockIdx.y*128, nBase = blockIdx.x*128;
    int wm = wid>>1, wn = wid&1;

    const __nv_bfloat16* Ahp = g_vs_h;
    const __nv_bfloat16* Alp = g_vs_l;
    const __nv_bfloat16* Bhp = g_spT_h + (size_t)b*NN*NN;
    const __nv_bfloat16* Blp = g_spT_l + (size_t)b*NN*NN;

    float acc[2][8][4];
    #pragma unroll
    for (int i=0;i<2;i++)
        #pragma unroll
        for (int j=0;j<8;j++)
            #pragma unroll
            for (int q=0;q<4;q++) acc[i][j][q]=0.f;

    // issue one stage of cp.async (chunk c -> stage c%NSTAGE)
    #define ISSUE_STAGE(c_) do{ \
        int st_ = (c_)%NSTAGE; uint32_t stg_ = sb + st_*STG_BYTES; \
        int k0_ = (c_)*KCHUNK; \
        _Pragma("unroll") \
        for (int j_=0;j_<4;j_++){ \
            int op_ = j_*256+tid; int row_ = op_>>3, ch_ = op_&7; \
            int kk_ = k0_ + ch_*8; \
            uint32_t so_ = SWZ(row_*128 + ch_*16); \
            bool va_ = (kk_ < NN) && ((mBase+row_) < NN); \
            size_t ga_ = va_ ? ((size_t)(mBase+row_)*NN + kk_) : 0; \
            cpa16(stg_+OFF_AH+so_, Ahp+ga_, va_); \
            cpa16(stg_+OFF_AL+so_, Alp+ga_, va_); \
            bool vb_ = (kk_ < NN) && ((nBase+row_) < NN); \
            size_t gb_ = vb_ ? ((size_t)(nBase+row_)*NN + kk_) : 0; \
            cpa16(stg_+OFF_BH+so_, Bhp+gb_, vb_); \
            cpa16(stg_+OFF_BL+so_, Blp+gb_, vb_); \
        } \
        cpa_commit(); \
    }while(0)

    ISSUE_STAGE(0);
    ISSUE_STAGE(1);
    ISSUE_STAGE(2);

    for (int c=0;c<NCHUNK;c++){
        asm volatile("cp.async.wait_group 2;" ::: "memory");
        __syncthreads();
        uint32_t stg = sb + (c%NSTAGE)*STG_BYTES;
        #pragma unroll
        for (int ks=0;ks<4;ks++){
            uint32_t ah[2][4], al[2][4];
            #pragma unroll
            for (int mt=0;mt<2;mt++){
                int row = wm*32 + mt*16 + (lane&15);
                uint32_t bo = SWZ(row*128 + ks*32 + (lane>>4)*16);
                ldsm4(ah[mt], stg+OFF_AH+bo);
                ldsm4(al[mt], stg+OFF_AL+bo);
            }
            uint32_t bh[8][2], bl[8][2];
            #pragma unroll
            for (int nt=0;nt<8;nt++){
                int row = wn*64 + nt*8 + (lane&7);
                uint32_t bo = SWZ(row*128 + ks*32 + ((lane>>3)&1)*16);
                ldsm2(bh[nt], stg+OFF_BH+bo);
                ldsm2(bl[nt], stg+OFF_BL+bo);
            }
            #pragma unroll
            for (int mt=0;mt<2;mt++)
                #pragma unroll
                for (int nt=0;nt<8;nt++){
                    mma16816(acc[mt][nt], ah[mt], bh[nt]);
                    mma16816(acc[mt][nt], ah[mt], bl[nt]);
                    mma16816(acc[mt][nt], al[mt], bh[nt]);
                }
        }
        __syncthreads();
        if (c+NSTAGE < NCHUNK){ ISSUE_STAGE(c+NSTAGE); }
        else { cpa_commit(); }   // keep group accounting uniform
    }

    float* C = g_S + (size_t)b*NN*NN;
    int tig = lane&3, grp = lane>>2;
    #pragma unroll
    for (int mt=0;mt<2;mt++){
        int r0 = mBase + wm*32 + mt*16 + grp;
        int r1 = r0 + 8;
        #pragma unroll
        for (int nt=0;nt<8;nt++){
            int c0 = nBase + wn*64 + nt*8 + tig*2;
            if (c0 < NN){
                bool c1ok = (c0+1) < NN;
                if (r0 < NN){
                    C[(size_t)r0*NN + c0] = acc[mt][nt][0];
                    if (c1ok) C[(size_t)r0*NN + c0 + 1] = acc[mt][nt][1];
                }
                if (r1 < NN){
                    C[(size_t)r1*NN + c0] = acc[mt][nt][2];
                    if (c1ok) C[(size_t)r1*NN + c0 + 1] = acc[mt][nt][3];
                }
            }
        }
    }
}

// ---- fp32 SIMT GEMM (small GEMMs) ----
__device__ __forceinline__ void gemm_body(
    const float* __restrict__ Ag, const float* __restrict__ Bg,
    const float* __restrict__ Dg, float* __restrict__ Cg,
    int M, int Nc, int Kd,
    long long sA, long long sB, long long sD, long long sC,
    float alpha, float beta)
{
    __shared__ float As[16][128];
    __shared__ float Bs[16][128];
    int bz = blockIdx.z;
    const float* A = Ag + bz*sA;
    const float* B = Bg + bz*sB;
    int rowBase = blockIdx.y*128, colBase = blockIdx.x*128;
    int tid = threadIdx.x;
    int tx = tid & 15, ty = tid >> 4;
    unsigned long long acc[8][4];
    #pragma unroll
    for (int i=0;i<8;i++)
        #pragma unroll
        for (int j=0;j<4;j++) acc[i][j] = 0ull;
    int aRow = tid >> 2, aCol = (tid & 3) << 2;
    int bRow = tid >> 5, bCol = (tid & 31) << 2;
    for (int k0 = 0; k0 < Kd; k0 += 16){
        #pragma unroll
        for (int r=0; r<2; r++){
            int lr = aRow + r*64;
            int grow = rowBase + lr;
            float4 v = make_float4(0.f,0.f,0.f,0.f);
            if (grow < M) v = *(const float4*)(A + (size_t)grow*Kd + k0 + aCol);
            As[aCol+0][lr]=v.x; As[aCol+1][lr]=v.y; As[aCol+2][lr]=v.z; As[aCol+3][lr]=v.w;
        }
        #pragma unroll
        for (int r=0; r<2; r++){
            int lr = bRow + r*8;
            int gcol = colBase + bCol;
            float4 v = make_float4(0.f,0.f,0.f,0.f);
            if (gcol < Nc) v = *(const float4*)(B + (size_t)(k0+lr)*Nc + gcol);
            *(float4*)&Bs[lr][bCol] = v;
        }
        __syncthreads();
        #pragma unroll
        for (int k=0; k<16; k++){
            float4 a0 = *(const float4*)&As[k][ty*8];
            float4 a1 = *(const float4*)&As[k][ty*8+4];
            unsigned long long av[8];
            av[0]=pack2(a0.x,a0.x); av[1]=pack2(a0.y,a0.y);
            av[2]=pack2(a0.z,a0.z); av[3]=pack2(a0.w,a0.w);
            av[4]=pack2(a1.x,a1.x); av[5]=pack2(a1.y,a1.y);
            av[6]=pack2(a1.z,a1.z); av[7]=pack2(a1.w,a1.w);
            unsigned long long bv[4];
            const unsigned long long* bp = (const unsigned long long*)&Bs[k][tx*8];
            bv[0]=bp[0]; bv[1]=bp[1]; bv[2]=bp[2]; bv[3]=bp[3];
            #pragma unroll
            for (int i=0;i<8;i++)
                #pragma unroll
                for (int j=0;j<4;j++) fma2(acc[i][j], av[i], bv[j]);
        }
        __syncthreads();
    }
    const float* D = Dg ? Dg + bz*sD : (const float*)0;
    float* C = Cg + bz*sC;
    #pragma unroll
    for (int i=0;i<8;i++){
        int grow = rowBase + ty*8 + i;
        if (grow >= M) continue;
        #pragma unroll
        for (int j=0;j<4;j++){
            float2 v = unpack2(acc[i][j]);
            int gc = colBase + tx*8 + j*2;
            if (gc < Nc){
                float r0 = alpha*v.x;
                if (D) r0 += beta*D[(size_t)grow*Nc + gc];
                C[(size_t)grow*Nc + gc] = r0;
            }
            if (gc+1 < Nc){
                float r1 = alpha*v.y;
                if (D) r1 += beta*D[(size_t)grow*Nc + gc + 1];
                C[(size_t)grow*Nc + gc + 1] = r1;
            }
        }
    }
}
__global__ void __launch_bounds__(256,2) gemm_xSAtt(){
    gemm_body(g_S, g_xTAt, (const float*)0, g_Tx0, NN, 256, NN,
              (long long)NN*NN, (long long)NN*256, 0LL, (long long)NN*256, 1.f, 0.f);
}
__global__ void __launch_bounds__(256,2) gemm_Tx1(const float* __restrict__ lap){
    gemm_body(lap, g_Tx0, (const float*)0, g_Tx1, NN, 256, NN,
              0LL, (long long)NN*256, 0LL, (long long)NN*256, 1.f, 0.f);
}
__global__ void __launch_bounds__(256,2) gemm_Tx2(const float* __restrict__ lap){
    gemm_body(lap, g_Tx1, g_Tx0, g_Tx2, NN, 256, NN,
              0LL, (long long)NN*256, (long long)NN*256, (long long)NN*256, 2.f, -1.f);
}

__global__ void k_softmax(){
    __shared__ float row[NN];
    __shared__ float red[256];
    int tid = threadIdx.x;
    size_t base = (size_t)blockIdx.x * NN;
    float m = -1e30f;
    for (int i = tid; i < NN; i += 256){ float v = g_S[base+i]; row[i]=v; m = fmaxf(m,v); }
    red[tid]=m; __syncthreads();
    for (int o=128;o>0;o>>=1){ if (tid<o) red[tid]=fmaxf(red[tid],red[tid+o]); __syncthreads(); }
    m = red[0]; __syncthreads();
    float s = 0.f;
    for (int i = tid; i < NN; i += 256){ float e = expf(row[i]-m); row[i]=e; s += e; }
    red[tid]=s; __syncthreads();
    for (int o=128;o>0;o>>=1){ if (tid<o) red[tid]+=red[tid+o]; __syncthreads(); }
    float inv = 1.f/red[0];
    for (int i = tid; i < NN; i += 256) g_S[base+i] = row[i]*inv;
}

__global__ void k_final(const float* __restrict__ x, const float* __restrict__ cheb,
                        const float* __restrict__ tw, const float* __restrict__ tb){
    int bn = blockIdx.x;
    int tid = threadIdx.x;
    __shared__ float xs[256], t0[256], t1[256], t2[256], ts0[16], ts1[16], ts2[16];
    size_t rb = (size_t)bn*256;
    xs[tid]=x[rb+tid]; t0[tid]=g_Tx0[rb+tid]; t1[tid]=g_Tx1[rb+tid]; t2[tid]=g_Tx2[rb+tid];
    __syncthreads();
    if (tid < 48){
        int kk = tid>>4, f = tid&15;
        const float* src = (kk==0) ? t0 : ((kk==1) ? t1 : t2);
        float s = 0.f;
        #pragma unroll
        for (int t=0;t<16;t++) s += src[f*16+t];
        float* dst = (kk==0) ? ts0 : ((kk==1) ? ts1 : ts2);
        dst[f] = s;
    }
    __syncthreads();
    if (tid < 16){
        int o = tid;
        float tm = 0.f;
        #pragma unroll
        for (int c=0;c<16;c++)
            #pragma unroll
            for (int t=0;t<16;t++) tm += xs[c*16+t]*tw[(o*16+c)*16+t];
        float sp = 0.f;
        #pragma unroll
        for (int f=0;f<16;f++)
            sp += ts0[f]*cheb[f*16+o] + ts1[f]*cheb[256+f*16+o] + ts2[f]*cheb[512+f*16+o];
        g_y[bn*16+o] = sp*(1.f/16.f) + tm + tb[o] + xs[o*16+15];
    }
}

__global__ void k_stats(){
    int b = blockIdx.x, tid = threadIdx.x;
    double s = 0.0, ss = 0.0;
    for (int i = tid; i < NN*OO; i += 256){
        float v = g_y[b*NN*OO + i];
        s += (double)v; ss += (double)v*(double)v;
    }
    __shared__ double rs[256], rq[256];
    rs[tid]=s; rq[tid]=ss; __syncthreads();
    for (int o=128;o>0;o>>=1){ if (tid<o){ rs[tid]+=rs[tid+o]; rq[tid]+=rq[tid+o]; } __syncthreads(); }
    if (tid==0){
        double mean = rs[0]/(double)(NN*OO);
        double var  = rq[0]/(double)(NN*OO) - mean*mean;
        g_stats[b*2]   = (float)mean;
        g_stats[b*2+1] = (float)(1.0/sqrt(var + 1e-5));
    }
}
__global__ void k_out(const float* __restrict__ lng, const float* __restrict__ lnb,
                      float* __restrict__ out){
    int i = blockIdx.x*256 + threadIdx.x;
    if (i < BB*NN*OO){
        int b  = i / (NN*OO);
        int no = i % (NN*OO);
        float v = (g_y[i]-g_stats[b*2])*g_stats[b*2+1]*lng[no] + lnb[no];
        out[i] = fmaxf(v, 0.f);
    }
}

extern "C" void kernel_launch(void* const* d_in, const int* in_sizes, int n_in,
                              void* d_out, int out_size){
    const float* x    = (const float*)d_in[0];
    const float* lap  = (const float*)d_in[1];
    const float* W1   = (const float*)d_in[2];
    const float* W2   = (const float*)d_in[3];
    const float* W3   = (const float*)d_in[4];
    const float* bs   = (const float*)d_in[5];
    const float* Vs   = (const float*)d_in[6];
    const float* U1   = (const float*)d_in[7];
    const float* U2   = (const float*)d_in[8];
    const float* U3   = (const float*)d_in[9];
    const float* be   = (const float*)d_in[10];
    const float* Ve   = (const float*)d_in[11];
    const float* cheb = (const float*)d_in[12];
    const float* tw   = (const float*)d_in[13];
    const float* tb   = (const float*)d_in[14];
    const float* lng  = (const float*)d_in[15];
    const float* lnb  = (const float*)d_in[16];
    float* out = (float*)d_out;

    static int smem_set = 0;
    if (!smem_set){
        cudaFuncSetAttribute(gemm_S_mma, cudaFuncAttributeMaxDynamicSharedMemorySize, SMEM_REQ);
        smem_set = 1;
    }

    k_u2u3<<<(NN+255)/256, 256>>>(U2, U3);
    k_tred<<<BB*TT, 256>>>(x, U1);
    k_E<<<1, 256>>>(Ve, be);
    k_xTAt<<<BB*NN, 256>>>(x, W1, W2, W3);
    k_vs_split<<<(NN*NN+255)/256, 256>>>(Vs);
    k_sigP<<<dim3(125,125,BB), 256>>>(bs);
    gemm_S_mma<<<dim3(32,32,BB), 256, SMEM_REQ>>>();
    k_softmax<<<BB*NN, 256>>>();
    gemm_xSAtt<<<dim3(2,32,BB), 256>>>();
    gemm_Tx1<<<dim3(2,32,BB), 256>>>(lap);
    gemm_Tx2<<<dim3(2,32,BB), 256>>>(lap);
    k_final<<<BB*NN, 256>>>(x, cheb, tw, tb);
    k_stats<<<BB, 256>>>();
    k_out<<<(BB*NN*OO+255)/256, 256>>>(lng, lnb, out);
}

// round 6
// speedup vs baseline: 2.5826x; 1.2869x over previous
#include <cuda_runtime.h>
#include <cuda_bf16.h>
#include <math.h>
#include <stdint.h>

#define NN 4000
#define BB 4
#define FF 16
#define TT 16
#define OO 16

__device__ float g_u2u3[NN];
__device__ float g_tlhs[BB*TT];
__device__ float g_trhs[BB*TT];
__device__ float g_E[BB*TT*TT];
__device__ float g_xTAt[BB*NN*FF*TT];
__device__ float g_slhs[BB*NN*FF];
__device__ float g_srhs[BB*NN*FF];
__device__ __align__(256) __nv_bfloat16 g_vs_h[(size_t)NN*NN];
__device__ __align__(256) __nv_bfloat16 g_vs_l[(size_t)NN*NN];
__device__ __align__(256) __nv_bfloat16 g_spT_h[(size_t)BB*NN*NN]; // sigP^T pre-gemm; softmaxed S post
__device__ __align__(256) __nv_bfloat16 g_spT_l[(size_t)BB*NN*NN];
__device__ __align__(256) __nv_bfloat16 g_lap_h[(size_t)NN*NN];
__device__ __align__(256) __nv_bfloat16 g_lap_l[(size_t)NN*NN];
__device__ __align__(256) __nv_bfloat16 g_bT_h[(size_t)BB*256*NN];  // transposed B panels
__device__ __align__(256) __nv_bfloat16 g_bT_l[(size_t)BB*256*NN];
__device__ __align__(256) float g_S[(size_t)BB*NN*NN];
__device__ float g_Tx0[BB*NN*FF*TT];
__device__ float g_Tx1[BB*NN*FF*TT];
__device__ float g_Tx2[BB*NN*FF*TT];
__device__ float g_y[BB*NN*OO];
__device__ float g_stats[BB*2];

__device__ __forceinline__ float sigmoidf_(float v){ return 1.f/(1.f+__expf(-v)); }

// ---- ptx helpers (sm_80-generic) ----
__device__ __forceinline__ uint32_t smem_u32(const void* p){
    uint32_t a;
    asm("{ .reg .u64 t; cvta.to.shared.u64 t, %1; cvt.u32.u64 %0, t; }" : "=r"(a) : "l"(p));
    return a;
}
#define SWZ(o) ((uint32_t)(o) ^ ((((uint32_t)(o)) >> 3) & 0x70u))
__device__ __forceinline__ void cpa16(uint32_t dst, const void* src, bool p){
    int sz = p ? 16 : 0;
    asm volatile("cp.async.cg.shared.global [%0], [%1], 16, %2;" :: "r"(dst), "l"(src), "r"(sz) : "memory");
}
__device__ __forceinline__ void cpa_commit(){ asm volatile("cp.async.commit_group;" ::: "memory"); }
__device__ __forceinline__ void ldsm4(uint32_t* r, uint32_t addr){
    asm volatile("ldmatrix.sync.aligned.m8n8.x4.shared.b16 {%0,%1,%2,%3}, [%4];"
        : "=r"(r[0]),"=r"(r[1]),"=r"(r[2]),"=r"(r[3]) : "r"(addr));
}
__device__ __forceinline__ void ldsm2(uint32_t* r, uint32_t addr){
    asm volatile("ldmatrix.sync.aligned.m8n8.x2.shared.b16 {%0,%1}, [%2];"
        : "=r"(r[0]),"=r"(r[1]) : "r"(addr));
}
__device__ __forceinline__ void mma16816(float* c, const uint32_t* a, const uint32_t* b){
    asm volatile("mma.sync.aligned.m16n8k16.row.col.f32.bf16.bf16.f32 "
        "{%0,%1,%2,%3}, {%4,%5,%6,%7}, {%8,%9}, {%0,%1,%2,%3};"
        : "+f"(c[0]),"+f"(c[1]),"+f"(c[2]),"+f"(c[3])
        : "r"(a[0]),"r"(a[1]),"r"(a[2]),"r"(a[3]), "r"(b[0]),"r"(b[1]));
}

// ---- small kernels ----
__global__ void k_u2u3(const float* __restrict__ U2, const float* __restrict__ U3){
    int n = blockIdx.x*blockDim.x + threadIdx.x;
    if (n < NN){
        float s = 0.f;
        #pragma unroll
        for (int g=0; g<FF; g++) s += U2[g*NN+n]*U3[g];
        g_u2u3[n] = s;
    }
}
__global__ void k_tred(const float* __restrict__ x, const float* __restrict__ U1){
    int b = blockIdx.x >> 4, t = blockIdx.x & 15;
    int tid = threadIdx.x;
    float s1 = 0.f, s2 = 0.f;
    for (int i = tid; i < NN*FF; i += 256){
        int n = i >> 4, f = i & 15;
        float v = x[((size_t)(b*NN+n)*FF+f)*TT + t];
        s1 += v*U1[n]; s2 += v*g_u2u3[n];
    }
    __shared__ float r1[256], r2[256];
    r1[tid]=s1; r2[tid]=s2; __syncthreads();
    for (int o=128; o>0; o>>=1){
        if (tid<o){ r1[tid]+=r1[tid+o]; r2[tid]+=r2[tid+o]; }
        __syncthreads();
    }
    if (tid==0){ g_tlhs[b*TT+t]=r1[0]; g_trhs[b*TT+t]=r2[0]; }
}
__global__ void k_E(const float* __restrict__ Ve, const float* __restrict__ be){
    __shared__ float tl[BB*TT], tr[BB*TT], sVe[TT*TT], sbe[TT*TT], Eb[BB*TT*TT];
    int tid = threadIdx.x;
    if (tid < BB*TT){ tl[tid]=g_tlhs[tid]; tr[tid]=g_trhs[tid]; }
    if (tid < TT*TT){ sVe[tid]=Ve[tid]; sbe[tid]=be[tid]; }
    __syncthreads();
    for (int idx = tid; idx < BB*TT*TT; idx += 256){
        int b = idx>>8, t = (idx>>4)&15, r = idx&15;
        float s = 0.f;
        #pragma unroll
        for (int ss=0; ss<TT; ss++)
            s += sVe[t*TT+ss]*(1.f/(1.f+expf(-(tl[b*TT+ss]*tr[b*TT+r] + sbe[ss*TT+r]))));
        Eb[idx] = s;
    }
    __syncthreads();
    if (tid < BB*TT){
        int base = tid*TT;
        float m = -1e30f;
        for (int r=0;r<TT;r++) m = fmaxf(m, Eb[base+r]);
        float e[TT]; float sum = 0.f;
        for (int r=0;r<TT;r++){ e[r]=expf(Eb[base+r]-m); sum+=e[r]; }
        float inv = 1.f/sum;
        for (int r=0;r<TT;r++) g_E[base+r] = e[r]*inv;
    }
}
__global__ void k_xTAt(const float* __restrict__ x, const float* __restrict__ W1,
                       const float* __restrict__ W2, const float* __restrict__ W3){
    int bn = blockIdx.x;
    int b = bn / NN;
    int tid = threadIdx.x;
    __shared__ float xs[256], Es[256], sr0[16];
    xs[tid] = x[(size_t)bn*256 + tid];
    Es[tid] = g_E[b*256 + tid];
    __syncthreads();
    int f = tid >> 4, t = tid & 15;
    float s = 0.f;
    #pragma unroll
    for (int ss=0; ss<TT; ss++) s += Es[t*16+ss]*xs[f*16+ss];
    g_xTAt[(size_t)bn*256 + tid] = s;
    if (tid < 16){
        float a=0.f, c=0.f;
        #pragma unroll
        for (int t2=0;t2<16;t2++){ float v = xs[tid*16+t2]; a += v*W1[t2]; c += v*W3[t2]; }
        g_slhs[bn*16+tid] = a;
        sr0[tid] = c;
    }
    __syncthreads();
    if (tid < 16){
        float g = 0.f;
        #pragma unroll
        for (int kk=0;kk<16;kk++) g += W2[tid*16+kk]*sr0[kk];
        g_srhs[bn*16+tid] = g;
    }
}
__global__ void k_vs_split(const float* __restrict__ Vs){
    size_t i = (size_t)blockIdx.x*256 + threadIdx.x;
    if (i < (size_t)NN*NN){
        float v = Vs[i];
        __nv_bfloat16 h = __float2bfloat16(v);
        g_vs_h[i] = h;
        g_vs_l[i] = __float2bfloat16(v - __bfloat162float(h));
    }
}
__global__ void k_lap_split(const float* __restrict__ lap){
    size_t i = (size_t)blockIdx.x*256 + threadIdx.x;
    if (i < (size_t)NN*NN){
        float v = lap[i];
        __nv_bfloat16 h = __float2bfloat16(v);
        g_lap_h[i] = h;
        g_lap_l[i] = __float2bfloat16(v - __bfloat162float(h));
    }
}
// transpose-split: X [b][NN][256] fp32 -> XT [b][256][NN] bf16 h/l
__global__ void k_tsplit(const float* __restrict__ X){
    int b = blockIdx.z;
    int m0 = blockIdx.x*32, c0 = blockIdx.y*32;
    int tx = threadIdx.x & 31, ty = threadIdx.x >> 5;   // 256 threads: 8 rows x 4 iters
    __shared__ float t[32][33];
    const float* Xb = X + (size_t)b*NN*256;
    #pragma unroll
    for (int i=0;i<4;i++){
        int row = ty + i*8;
        t[row][tx] = Xb[(size_t)(m0+row)*256 + c0 + tx];
    }
    __syncthreads();
    __nv_bfloat16* Th = g_bT_h + (size_t)b*256*NN;
    __nv_bfloat16* Tl = g_bT_l + (size_t)b*256*NN;
    #pragma unroll
    for (int i=0;i<4;i++){
        int row = ty + i*8;            // output row = c0+row, col = m0+tx
        float v = t[tx][row];
        __nv_bfloat16 h = __float2bfloat16(v);
        size_t o = (size_t)(c0+row)*NN + m0 + tx;
        Th[o] = h;
        Tl[o] = __float2bfloat16(v - __bfloat162float(h));
    }
}
// sigmoid(prod+bs) - 0.5, transposed [b][k][m], bf16 hi/lo
__global__ void k_sigP(const float* __restrict__ bs){
    int b = blockIdx.z;
    int m0 = blockIdx.y*32, k0 = blockIdx.x*32;
    int tid = threadIdx.x;
    __shared__ float Lm[32][17], Rk[32][17], sbs[32][33];
    for (int i = tid; i < 512; i += 256){
        int r = i>>4, c = i&15;
        Lm[r][c] = g_slhs[(b*NN + m0 + r)*16 + c];
        Rk[r][c] = g_srhs[(b*NN + k0 + r)*16 + c];
    }
    for (int i = tid; i < 1024; i += 256){
        int mi = i>>5, ki = i&31;
        sbs[mi][ki] = bs[(size_t)(m0+mi)*NN + k0 + ki];
    }
    __syncthreads();
    for (int e = tid; e < 1024; e += 256){
        int ki = e>>5, mi = e&31;
        float d = sbs[mi][ki];
        #pragma unroll
        for (int f=0; f<16; f++) d += Lm[mi][f]*Rk[ki][f];
        float s = sigmoidf_(d) - 0.5f;
        __nv_bfloat16 h = __float2bfloat16(s);
        size_t o = (size_t)b*NN*NN + (size_t)(k0+ki)*NN + (m0+mi);
        g_spT_h[o] = h;
        g_spT_l[o] = __float2bfloat16(s - __bfloat162float(h));
    }
}

// ---- generic bf16-split tensor GEMM (3-pass hh+hl+lh), 128x128 CTA tile ----
#define KCHUNK 64
#define NSTAGE 3
#define STG_BYTES 65536
#define OFF_AH 0
#define OFF_AL 16384
#define OFF_BH 32768
#define OFF_BL 49152
#define NCHUNK 63
#define SMEM_REQ (NSTAGE*STG_BYTES + 1024)

__global__ void __launch_bounds__(256,1) gemm_bsplit(
    const __nv_bfloat16* __restrict__ gAh, const __nv_bfloat16* __restrict__ gAl, long long sAb,
    const __nv_bfloat16* __restrict__ gBh, const __nv_bfloat16* __restrict__ gBl, long long sBb,
    float* __restrict__ gC, const float* __restrict__ gD, long long sCb,
    int ldc, int Ncols, float alpha, float beta)
{
    extern __shared__ char dsm[];
    uint32_t sb = (smem_u32(dsm) + 1023u) & ~1023u;
    int tid = threadIdx.x, lane = tid&31, wid = tid>>5;
    int b = blockIdx.z;
    int mBase = blockIdx.y*128, nBase = blockIdx.x*128;
    int wm = wid>>1, wn = wid&1;

    const __nv_bfloat16* Ahp = gAh + (size_t)b*sAb;
    const __nv_bfloat16* Alp = gAl + (size_t)b*sAb;
    const __nv_bfloat16* Bhp = gBh + (size_t)b*sBb;
    const __nv_bfloat16* Blp = gBl + (size_t)b*sBb;

    float acc[2][8][4];
    #pragma unroll
    for (int i=0;i<2;i++)
        #pragma unroll
        for (int j=0;j<8;j++)
            #pragma unroll
            for (int q=0;q<4;q++) acc[i][j][q]=0.f;

    #define ISSUE_STAGE(c_) do{ \
        int st_ = (c_)%NSTAGE; uint32_t stg_ = sb + st_*STG_BYTES; \
        int k0_ = (c_)*KCHUNK; \
        _Pragma("unroll") \
        for (int j_=0;j_<4;j_++){ \
            int op_ = j_*256+tid; int row_ = op_>>3, ch_ = op_&7; \
            int kk_ = k0_ + ch_*8; \
            uint32_t so_ = SWZ(row_*128 + ch_*16); \
            bool va_ = (kk_ < NN) && ((mBase+row_) < NN); \
            size_t ga_ = va_ ? ((size_t)(mBase+row_)*NN + kk_) : 0; \
            cpa16(stg_+OFF_AH+so_, Ahp+ga_, va_); \
            cpa16(stg_+OFF_AL+so_, Alp+ga_, va_); \
            bool vb_ = (kk_ < NN) && ((nBase+row_) < Ncols); \
            size_t gb_ = vb_ ? ((size_t)(nBase+row_)*NN + kk_) : 0; \
            cpa16(stg_+OFF_BH+so_, Bhp+gb_, vb_); \
            cpa16(stg_+OFF_BL+so_, Blp+gb_, vb_); \
        } \
        cpa_commit(); \
    }while(0)

    ISSUE_STAGE(0);
    ISSUE_STAGE(1);
    ISSUE_STAGE(2);

    for (int c=0;c<NCHUNK;c++){
        asm volatile("cp.async.wait_group 2;" ::: "memory");
        __syncthreads();
        uint32_t stg = sb + (c%NSTAGE)*STG_BYTES;
        #pragma unroll
        for (int ks=0;ks<4;ks++){
            uint32_t ah[2][4], al[2][4];
            #pragma unroll
            for (int mt=0;mt<2;mt++){
                int row = wm*32 + mt*16 + (lane&15);
                uint32_t bo = SWZ(row*128 + ks*32 + (lane>>4)*16);
                ldsm4(ah[mt], stg+OFF_AH+bo);
                ldsm4(al[mt], stg+OFF_AL+bo);
            }
            uint32_t bh[8][2], bl[8][2];
            #pragma unroll
            for (int nt=0;nt<8;nt++){
                int row = wn*64 + nt*8 + (lane&7);
                uint32_t bo = SWZ(row*128 + ks*32 + ((lane>>3)&1)*16);
                ldsm2(bh[nt], stg+OFF_BH+bo);
                ldsm2(bl[nt], stg+OFF_BL+bo);
            }
            #pragma unroll
            for (int mt=0;mt<2;mt++)
                #pragma unroll
                for (int nt=0;nt<8;nt++){
                    mma16816(acc[mt][nt], ah[mt], bh[nt]);
                    mma16816(acc[mt][nt], ah[mt], bl[nt]);
                    mma16816(acc[mt][nt], al[mt], bh[nt]);
                }
        }
        __syncthreads();
        if (c+NSTAGE < NCHUNK){ ISSUE_STAGE(c+NSTAGE); }
        else { cpa_commit(); }
    }
    #undef ISSUE_STAGE

    float* C = gC + (size_t)b*sCb;
    const float* D = gD ? gD + (size_t)b*sCb : (const float*)0;
    int tig = lane&3, grp = lane>>2;
    #pragma unroll
    for (int mt=0;mt<2;mt++){
        int r0 = mBase + wm*32 + mt*16 + grp;
        int r1 = r0 + 8;
        #pragma unroll
        for (int nt=0;nt<8;nt++){
            int c0 = nBase + wn*64 + nt*8 + tig*2;
            if (c0 < Ncols){
                bool c1ok = (c0+1) < Ncols;
                if (r0 < NN){
                    float v0 = alpha*acc[mt][nt][0];
                    if (D) v0 += beta*D[(size_t)r0*ldc + c0];
                    C[(size_t)r0*ldc + c0] = v0;
                    if (c1ok){
                        float v1 = alpha*acc[mt][nt][1];
                        if (D) v1 += beta*D[(size_t)r0*ldc + c0 + 1];
                        C[(size_t)r0*ldc + c0 + 1] = v1;
                    }
                }
                if (r1 < NN){
                    float v2 = alpha*acc[mt][nt][2];
                    if (D) v2 += beta*D[(size_t)r1*ldc + c0];
                    C[(size_t)r1*ldc + c0] = v2;
                    if (c1ok){
                        float v3 = alpha*acc[mt][nt][3];
                        if (D) v3 += beta*D[(size_t)r1*ldc + c0 + 1];
                        C[(size_t)r1*ldc + c0 + 1] = v3;
                    }
                }
            }
        }
    }
}

// softmax over last dim of S; writes bf16 h/l split (A operand of xSAtt) into g_spT
__global__ void k_softmax(){
    __shared__ float row[NN];
    __shared__ float red[256];
    int tid = threadIdx.x;
    size_t base = (size_t)blockIdx.x * NN;
    float m = -1e30f;
    for (int i = tid; i < NN; i += 256){ float v = g_S[base+i]; row[i]=v; m = fmaxf(m,v); }
    red[tid]=m; __syncthreads();
    for (int o=128;o>0;o>>=1){ if (tid<o) red[tid]=fmaxf(red[tid],red[tid+o]); __syncthreads(); }
    m = red[0]; __syncthreads();
    float s = 0.f;
    for (int i = tid; i < NN; i += 256){ float e = __expf(row[i]-m); row[i]=e; s += e; }
    red[tid]=s; __syncthreads();
    for (int o=128;o>0;o>>=1){ if (tid<o) red[tid]+=red[tid+o]; __syncthreads(); }
    float inv = 1.f/red[0];
    for (int i = tid; i < NN; i += 256){
        float p = row[i]*inv;
        __nv_bfloat16 h = __float2bfloat16(p);
        g_spT_h[base+i] = h;
        g_spT_l[base+i] = __float2bfloat16(p - __bfloat162float(h));
    }
}

__global__ void k_final(const float* __restrict__ x, const float* __restrict__ cheb,
                        const float* __restrict__ tw, const float* __restrict__ tb){
    int bn = blockIdx.x;
    int tid = threadIdx.x;
    __shared__ float xs[256], t0[256], t1[256], t2[256], ts0[16], ts1[16], ts2[16];
    size_t rb = (size_t)bn*256;
    xs[tid]=x[rb+tid]; t0[tid]=g_Tx0[rb+tid]; t1[tid]=g_Tx1[rb+tid]; t2[tid]=g_Tx2[rb+tid];
    __syncthreads();
    if (tid < 48){
        int kk = tid>>4, f = tid&15;
        const float* src = (kk==0) ? t0 : ((kk==1) ? t1 : t2);
        float s = 0.f;
        #pragma unroll
        for (int t=0;t<16;t++) s += src[f*16+t];
        float* dst = (kk==0) ? ts0 : ((kk==1) ? ts1 : ts2);
        dst[f] = s;
    }
    __syncthreads();
    if (tid < 16){
        int o = tid;
        float tm = 0.f;
        #pragma unroll
        for (int c=0;c<16;c++)
            #pragma unroll
            for (int t=0;t<16;t++) tm += xs[c*16+t]*tw[(o*16+c)*16+t];
        float sp = 0.f;
        #pragma unroll
        for (int f=0;f<16;f++)
            sp += ts0[f]*cheb[f*16+o] + ts1[f]*cheb[256+f*16+o] + ts2[f]*cheb[512+f*16+o];
        g_y[bn*16+o] = sp*(1.f/16.f) + tm + tb[o] + xs[o*16+15];
    }
}

__global__ void k_stats(){
    int b = blockIdx.x, tid = threadIdx.x;
    double s = 0.0, ss = 0.0;
    for (int i = tid; i < NN*OO; i += 256){
        float v = g_y[b*NN*OO + i];
        s += (double)v; ss += (double)v*(double)v;
    }
    __shared__ double rs[256], rq[256];
    rs[tid]=s; rq[tid]=ss; __syncthreads();
    for (int o=128;o>0;o>>=1){ if (tid<o){ rs[tid]+=rs[tid+o]; rq[tid]+=rq[tid+o]; } __syncthreads(); }
    if (tid==0){
        double mean = rs[0]/(double)(NN*OO);
        double var  = rq[0]/(double)(NN*OO) - mean*mean;
        g_stats[b*2]   = (float)mean;
        g_stats[b*2+1] = (float)(1.0/sqrt(var + 1e-5));
    }
}
__global__ void k_out(const float* __restrict__ lng, const float* __restrict__ lnb,
                      float* __restrict__ out){
    int i = blockIdx.x*256 + threadIdx.x;
    if (i < BB*NN*OO){
        int b  = i / (NN*OO);
        int no = i % (NN*OO);
        float v = (g_y[i]-g_stats[b*2])*g_stats[b*2+1]*lng[no] + lnb[no];
        out[i] = fmaxf(v, 0.f);
    }
}

extern "C" void kernel_launch(void* const* d_in, const int* in_sizes, int n_in,
                              void* d_out, int out_size){
    const float* x    = (const float*)d_in[0];
    const float* lap  = (const float*)d_in[1];
    const float* W1   = (const float*)d_in[2];
    const float* W2   = (const float*)d_in[3];
    const float* W3   = (const float*)d_in[4];
    const float* bs   = (const float*)d_in[5];
    const float* Vs   = (const float*)d_in[6];
    const float* U1   = (const float*)d_in[7];
    const float* U2   = (const float*)d_in[8];
    const float* U3   = (const float*)d_in[9];
    const float* be   = (const float*)d_in[10];
    const float* Ve   = (const float*)d_in[11];
    const float* cheb = (const float*)d_in[12];
    const float* tw   = (const float*)d_in[13];
    const float* tb   = (const float*)d_in[14];
    const float* lng  = (const float*)d_in[15];
    const float* lnb  = (const float*)d_in[16];
    float* out = (float*)d_out;

    static int smem_set = 0;
    if (!smem_set){
        cudaFuncSetAttribute(gemm_bsplit, cudaFuncAttributeMaxDynamicSharedMemorySize, SMEM_REQ);
        smem_set = 1;
    }

    float *g_Sp, *g_T0p, *g_T1p, *g_T2p, *g_xTp;
    __nv_bfloat16 *vs_h_p, *vs_l_p, *spT_h_p, *spT_l_p, *lap_h_p, *lap_l_p, *bT_h_p, *bT_l_p;
    cudaGetSymbolAddress((void**)&g_Sp,  g_S);
    cudaGetSymbolAddress((void**)&g_T0p, g_Tx0);
    cudaGetSymbolAddress((void**)&g_T1p, g_Tx1);
    cudaGetSymbolAddress((void**)&g_T2p, g_Tx2);
    cudaGetSymbolAddress((void**)&g_xTp, g_xTAt);
    cudaGetSymbolAddress((void**)&vs_h_p,  g_vs_h);
    cudaGetSymbolAddress((void**)&vs_l_p,  g_vs_l);
    cudaGetSymbolAddress((void**)&spT_h_p, g_spT_h);
    cudaGetSymbolAddress((void**)&spT_l_p, g_spT_l);
    cudaGetSymbolAddress((void**)&lap_h_p, g_lap_h);
    cudaGetSymbolAddress((void**)&lap_l_p, g_lap_l);
    cudaGetSymbolAddress((void**)&bT_h_p,  g_bT_h);
    cudaGetSymbolAddress((void**)&bT_l_p,  g_bT_l);

    k_u2u3<<<(NN+255)/256, 256>>>(U2, U3);
    k_tred<<<BB*TT, 256>>>(x, U1);
    k_E<<<1, 256>>>(Ve, be);
    k_xTAt<<<BB*NN, 256>>>(x, W1, W2, W3);
    k_vs_split<<<(NN*NN+255)/256, 256>>>(Vs);
    k_lap_split<<<(NN*NN+255)/256, 256>>>(lap);
    k_sigP<<<dim3(125,125,BB), 256>>>(bs);

    // S = Vs @ sigP'   (big GEMM)
    gemm_bsplit<<<dim3(32,32,BB), 256, SMEM_REQ>>>(
        vs_h_p, vs_l_p, 0LL, spT_h_p, spT_l_p, (long long)NN*NN,
        g_Sp, (const float*)0, (long long)NN*NN, NN, NN, 1.f, 0.f);

    k_softmax<<<BB*NN, 256>>>();                 // -> bf16 split into g_spT
    k_tsplit<<<dim3(125,8,BB), 256>>>(g_xTp);    // xTAt^T -> g_bT

    // Tx0 = softmax(S) @ xTAt
    gemm_bsplit<<<dim3(2,32,BB), 256, SMEM_REQ>>>(
        spT_h_p, spT_l_p, (long long)NN*NN, bT_h_p, bT_l_p, (long long)256*NN,
        g_T0p, (const float*)0, (long long)NN*256, 256, 256, 1.f, 0.f);

    k_tsplit<<<dim3(125,8,BB), 256>>>(g_T0p);    // Tx0^T -> g_bT

    // Tx1 = lap @ Tx0
    gemm_bsplit<<<dim3(2,32,BB), 256, SMEM_REQ>>>(
        lap_h_p, lap_l_p, 0LL, bT_h_p, bT_l_p, (long long)256*NN,
        g_T1p, (const float*)0, (long long)NN*256, 256, 256, 1.f, 0.f);

    k_tsplit<<<dim3(125,8,BB), 256>>>(g_T1p);    // Tx1^T -> g_bT

    // Tx2 = 2*lap @ Tx1 - Tx0
    gemm_bsplit<<<dim3(2,32,BB), 256, SMEM_REQ>>>(
        lap_h_p, lap_l_p, 0LL, bT_h_p, bT_l_p, (long long)256*NN,
        g_T2p, g_T0p, (long long)NN*256, 256, 256, 2.f, -1.f);

    k_final<<<BB*NN, 256>>>(x, cheb, tw, tb);
    k_stats<<<BB, 256>>>();
    k_out<<<(BB*NN*OO+255)/256, 256>>>(lng, lnb, out);
}